// round 11
// baseline (speedup 1.0000x reference)
#include <cuda_runtime.h>
#include <cstdint>

// SpectralConv1d via mma.sync (HMMA) bf16 2-way-split GEMM. Round 11.
// R11: cp.async double-buffered pipeline, raw-fp32 stage with split-at-use,
//      m16n64 warp tile, 3 CTAs/SM.

#define THREADS 256
#define KT      8
#define TROWS   16                      // rows per tile
#define TILES   8                       // 128 rows per CTA
#define RS      258                     // u64 per stage row (even -> 16B align)
#define BUFB    (TROWS * RS * 8)        // 33024 bytes per buffer
#define SMEM_BYTES (2 * BUFB)           // 66048

__device__ unsigned long long gB[8 * 16384];  // [kgi][md][s][ks][j][lane][2] u64

__device__ __forceinline__ unsigned smem_u32(const void* p) {
    unsigned a;
    asm("{ .reg .u64 t; cvta.to.shared.u64 t, %1; cvt.u32.u64 %0, t; }" : "=r"(a) : "l"(p));
    return a;
}
__device__ __forceinline__ unsigned cvt2bf(float lo, float hi) {
    unsigned r;
    asm("cvt.rn.bf16x2.f32 %0, %1, %2;" : "=r"(r) : "f"(hi), "f"(lo));
    return r;
}
__device__ __forceinline__ unsigned long long pack2(float lo, float hi) {
    unsigned long long r;
    asm("mov.b64 %0, {%1, %2};" : "=l"(r) : "f"(lo), "f"(hi));
    return r;
}
__device__ __forceinline__ unsigned long long lds64(unsigned a) {
    unsigned long long v;
    asm volatile("ld.shared.b64 %0, [%1];" : "=l"(v) : "r"(a));
    return v;
}
__device__ __forceinline__ void sts64(unsigned a, unsigned long long v) {
    asm volatile("st.shared.b64 [%0], %1;" :: "r"(a), "l"(v));
}
__device__ __forceinline__ void cp_async16(unsigned dst, const void* src) {
    asm volatile("cp.async.ca.shared.global [%0], [%1], 16;\n" :: "r"(dst), "l"(src));
}
__device__ __forceinline__ void cp_commit() { asm volatile("cp.async.commit_group;\n"); }
__device__ __forceinline__ void cp_wait0()  { asm volatile("cp.async.wait_group 0;\n"); }
__device__ __forceinline__ void cp_wait1()  { asm volatile("cp.async.wait_group 1;\n"); }
__device__ __forceinline__ void mma16816(float* c, const unsigned* a,
                                         unsigned b0, unsigned b1) {
    asm volatile(
        "mma.sync.aligned.m16n8k16.row.col.f32.bf16.bf16.f32 "
        "{%0,%1,%2,%3}, {%4,%5,%6,%7}, {%8,%9}, {%0,%1,%2,%3};"
        : "+f"(c[0]), "+f"(c[1]), "+f"(c[2]), "+f"(c[3])
        : "r"(a[0]), "r"(a[1]), "r"(a[2]), "r"(a[3]), "r"(b0), "r"(b1));
}

// ---- prep: B fragments, lane-consecutive layout (same as R10) ----
__global__ void __launch_bounds__(THREADS)
spectral_prepB_kernel(const float* __restrict__ W)
{
    const int kgi = blockIdx.x;                 // 0..7
    const int kbase = kgi * KT;
    unsigned* dst = reinterpret_cast<unsigned*>(gB + kgi * 16384);

    #pragma unroll
    for (int it = 0; it < 32; ++it) {
        int idx = threadIdx.x + it * THREADS;   // 8192 = (o,i,md)
        int md = idx & 7, i = (idx >> 3) & 31, o = idx >> 8;
        float2 wv = *reinterpret_cast<const float2*>(
            W + (size_t)o * 4096 + i * 128 + (size_t)(kbase + md) * 2);
        unsigned ph = cvt2bf(wv.x, wv.y);       // low=wr_h, high=wi_h
        float wrh = __uint_as_float(ph << 16);
        float wih = __uint_as_float(ph & 0xFFFF0000u);
        unsigned pl = cvt2bf(wv.x - wrh, wv.y - wih);
        const int ks = i >> 3, half = (i >> 2) & 1, t4 = i & 3;
        #pragma unroll
        for (int s = 0; s < 2; ++s) {
            unsigned p = s ? pl : ph;
            #pragma unroll
            for (int c = 0; c < 2; ++c) {       // n = 2o + c
                int n = 2 * o + c;
                int gid = n & 7, nt = n >> 3, j = nt >> 1, wsel = nt & 1;
                unsigned u64i =
                    (unsigned)(((((md * 2 + s) * 4 + ks) * 4 + j) * 32
                                + (gid * 4 + t4)) * 2 + wsel);
                unsigned val = c ? ((p >> 16) | (p << 16))    // (wi, wr)
                                 : (p ^ 0x80000000u);         // (wr, -wi)
                dst[u64i * 2 + half] = val;
            }
        }
    }
}

// ---- main ----
__global__ void __launch_bounds__(THREADS, 3)
spectral_r11_kernel(const float* __restrict__ X,
                    float* __restrict__ O)
{
    extern __shared__ char smem[];
    const unsigned sb = smem_u32(smem);

    const int tid  = threadIdx.x;
    const int lane = tid & 31;
    const int md   = tid >> 5;                  // warp == mode
    const int gid  = lane >> 2;
    const int t4   = lane & 3;
    const int kgi  = blockIdx.y;
    const int kg   = kgi * KT;
    const long rowBase = (long)blockIdx.x * (TROWS * TILES);

    // fill tile t into buffer base (raw fp32 pairs, 16B = 2 modes)
    auto fill = [&](int t, unsigned buf) {
        const float* base = X + (rowBase + (long)t * TROWS) * 4096 + (size_t)kg * 2;
        #pragma unroll
        for (int it = 0; it < 8; ++it) {
            int idx = tid + it * THREADS;       // 2048 = (row, i, md2)
            int md2 = idx & 3, i = (idx >> 2) & 31, row = idx >> 7;
            cp_async16(buf + (unsigned)(row * RS + i * 8 + ((2 * md2) ^ (i & 6))) * 8,
                       base + (size_t)row * 4096 + i * 128 + md2 * 4);
        }
        cp_commit();
    };

    fill(0, sb);
    fill(1, sb + BUFB);

    const unsigned long long* Bk = gB + kgi * 16384;

    #pragma unroll
    for (int t = 0; t < TILES; ++t) {
        const unsigned cur  = sb + (unsigned)(t & 1) * BUFB;
        char* curp = smem + (size_t)(t & 1) * BUFB;

        if (t == TILES - 1) cp_wait0(); else cp_wait1();
        __syncthreads();

        float acc[8][4];
        #pragma unroll
        for (int nt = 0; nt < 8; ++nt)
            #pragma unroll
            for (int q = 0; q < 4; ++q) acc[nt][q] = 0.0f;

        #pragma unroll
        for (int ks = 0; ks < 4; ++ks) {
            // B fragments: lane-consecutive LDG.128 (L1-resident)
            const ulonglong2* bh2 = reinterpret_cast<const ulonglong2*>(
                Bk + (size_t)((((md * 2 + 0) * 4 + ks) * 4) * 32 + lane) * 2);
            const ulonglong2* bl2 = reinterpret_cast<const ulonglong2*>(
                Bk + (size_t)((((md * 2 + 1) * 4 + ks) * 4) * 32 + lane) * 2);
            ulonglong2 BH[4], BL[4];
            #pragma unroll
            for (int j = 0; j < 4; ++j) { BH[j] = bh2[j * 32]; BL[j] = bl2[j * 32]; }

            // A fragments: raw fp32 LDS.64 + inline bf16 split
            unsigned ah[4], al[4];
            #pragma unroll
            for (int j = 0; j < 4; ++j) {
                int row = gid + (j & 1) * 8;
                int i   = t4 + (j >> 1) * 4 + 8 * ks;
                unsigned long long v =
                    lds64(cur + (unsigned)(row * RS + i * 8 + (md ^ (i & 6))) * 8);
                float xr, xi;
                asm("mov.b64 {%0,%1}, %2;" : "=f"(xr), "=f"(xi) : "l"(v));
                unsigned ph = cvt2bf(xr, xi);
                float xrh = __uint_as_float(ph << 16);
                float xih = __uint_as_float(ph & 0xFFFF0000u);
                ah[j] = ph;
                al[j] = cvt2bf(xr - xrh, xi - xih);
            }

            #pragma unroll
            for (int nt = 0; nt < 8; ++nt) {
                unsigned long long bh = (nt & 1) ? BH[nt >> 1].y : BH[nt >> 1].x;
                unsigned long long bl = (nt & 1) ? BL[nt >> 1].y : BL[nt >> 1].x;
                mma16816(acc[nt], ah, (unsigned)bh, (unsigned)(bh >> 32)); // hi*hi
                mma16816(acc[nt], al, (unsigned)bh, (unsigned)(bh >> 32)); // lo*hi
                mma16816(acc[nt], ah, (unsigned)bl, (unsigned)(bl >> 32)); // hi*lo
            }
        }
        __syncthreads();        // all reads of cur done -> reuse as out stage

        // out stage: [row][o][mdslot] u64 = (Re, Im), slot = md ^ (o&6)
        #pragma unroll
        for (int nt = 0; nt < 8; ++nt) {
            int o = nt * 4 + t4;
            unsigned so = (unsigned)(o * 8 + (md ^ (o & 6)));
            sts64(cur + (unsigned)(gid * RS) * 8 + so * 8,
                  pack2(acc[nt][0], acc[nt][1]));
            sts64(cur + (unsigned)((gid + 8) * RS) * 8 + so * 8,
                  pack2(acc[nt][2], acc[nt][3]));
        }
        __syncthreads();

        // coalesced store: 16B covers md pair; kpair permuted by slot xor
        const long trow = rowBase + (long)t * TROWS;
        #pragma unroll
        for (int it = 0; it < 8; ++it) {
            int g = tid + it * THREADS;         // 2048 = (row, o, q)
            int q = g & 3, o = (g >> 2) & 31, row = g >> 7;
            ulonglong2 v = *reinterpret_cast<ulonglong2*>(
                curp + (size_t)(row * RS + o * 8 + q * 2) * 8);
            int kpair = q ^ ((o >> 1) & 3);
            *reinterpret_cast<ulonglong2*>(
                O + (trow + row) * 4096 + (size_t)o * 128 + (size_t)(kg + 2 * kpair) * 2)
                = v;
        }

        if (t + 2 < TILES) {
            __syncthreads();    // STG reads done before refilling cur
            fill(t + 2, cur);
        }
    }
}

extern "C" void kernel_launch(void* const* d_in, const int* in_sizes, int n_in,
                              void* d_out, int out_size)
{
    const float* x = (const float*)d_in[0];   // (8,2048,32,64,2) fp32
    const float* w = (const float*)d_in[1];   // (32,32,64,2) fp32
    float* out = (float*)d_out;               // (8,2048,32,64,2) fp32

    spectral_prepB_kernel<<<8, THREADS>>>(w);

    cudaFuncSetAttribute(spectral_r11_kernel,
                         cudaFuncAttributeMaxDynamicSharedMemorySize, SMEM_BYTES);
    dim3 grid(16384 / (TROWS * TILES), 64 / KT);   // (128, 8) = 1024 CTAs
    spectral_r11_kernel<<<grid, THREADS, SMEM_BYTES>>>(x, out);
}

// round 12
// speedup vs baseline: 1.7463x; 1.7463x over previous
#include <cuda_runtime.h>
#include <cstdint>

// SpectralConv1d via mma.sync (HMMA) bf16 2-way-split GEMM. Round 12.
// R12 = R10 compute (m32 warp tile, transient B regs) + double-buffered
//       cp.async pipeline over 32-row tiles (fill t+2 overlaps compute/store).

#define THREADS 256
#define KT      8
#define TROWS   32                      // rows per tile
#define TILES   4                       // 128 rows per CTA
#define RS      258                     // u64 per stage row (16B-aligned pairs)
#define BUFB    (TROWS * RS * 8)        // 66048 bytes per buffer
#define SMEM_BYTES (2 * BUFB)           // 132096

__device__ unsigned long long gB[8 * 16384];  // [kgi][md][s][ks][j][lane][2] u64

__device__ __forceinline__ unsigned smem_u32(const void* p) {
    unsigned a;
    asm("{ .reg .u64 t; cvta.to.shared.u64 t, %1; cvt.u32.u64 %0, t; }" : "=r"(a) : "l"(p));
    return a;
}
__device__ __forceinline__ unsigned cvt2bf(float lo, float hi) {
    unsigned r;
    asm("cvt.rn.bf16x2.f32 %0, %1, %2;" : "=r"(r) : "f"(hi), "f"(lo));
    return r;
}
__device__ __forceinline__ unsigned long long pack2(float lo, float hi) {
    unsigned long long r;
    asm("mov.b64 %0, {%1, %2};" : "=l"(r) : "f"(lo), "f"(hi));
    return r;
}
__device__ __forceinline__ unsigned long long lds64(unsigned a) {
    unsigned long long v;
    asm volatile("ld.shared.b64 %0, [%1];" : "=l"(v) : "r"(a));
    return v;
}
__device__ __forceinline__ void sts64(unsigned a, unsigned long long v) {
    asm volatile("st.shared.b64 [%0], %1;" :: "r"(a), "l"(v));
}
__device__ __forceinline__ void cp_async16(unsigned dst, const void* src) {
    asm volatile("cp.async.ca.shared.global [%0], [%1], 16;\n" :: "r"(dst), "l"(src));
}
__device__ __forceinline__ void cp_commit() { asm volatile("cp.async.commit_group;\n"); }
__device__ __forceinline__ void cp_wait0()  { asm volatile("cp.async.wait_group 0;\n"); }
__device__ __forceinline__ void cp_wait1()  { asm volatile("cp.async.wait_group 1;\n"); }
__device__ __forceinline__ void mma16816(float* c, const unsigned* a,
                                         unsigned b0, unsigned b1) {
    asm volatile(
        "mma.sync.aligned.m16n8k16.row.col.f32.bf16.bf16.f32 "
        "{%0,%1,%2,%3}, {%4,%5,%6,%7}, {%8,%9}, {%0,%1,%2,%3};"
        : "+f"(c[0]), "+f"(c[1]), "+f"(c[2]), "+f"(c[3])
        : "r"(a[0]), "r"(a[1]), "r"(a[2]), "r"(a[3]), "r"(b0), "r"(b1));
}

// ---- prep: B fragments, lane-consecutive layout (same as R10/R11) ----
__global__ void __launch_bounds__(THREADS)
spectral_prepB_kernel(const float* __restrict__ W)
{
    const int kgi = blockIdx.x;                 // 0..7
    const int kbase = kgi * KT;
    unsigned* dst = reinterpret_cast<unsigned*>(gB + kgi * 16384);

    #pragma unroll
    for (int it = 0; it < 32; ++it) {
        int idx = threadIdx.x + it * THREADS;   // 8192 = (o,i,md)
        int md = idx & 7, i = (idx >> 3) & 31, o = idx >> 8;
        float2 wv = *reinterpret_cast<const float2*>(
            W + (size_t)o * 4096 + i * 128 + (size_t)(kbase + md) * 2);
        unsigned ph = cvt2bf(wv.x, wv.y);       // low=wr_h, high=wi_h
        float wrh = __uint_as_float(ph << 16);
        float wih = __uint_as_float(ph & 0xFFFF0000u);
        unsigned pl = cvt2bf(wv.x - wrh, wv.y - wih);
        const int ks = i >> 3, half = (i >> 2) & 1, t4 = i & 3;
        #pragma unroll
        for (int s = 0; s < 2; ++s) {
            unsigned p = s ? pl : ph;
            #pragma unroll
            for (int c = 0; c < 2; ++c) {       // n = 2o + c
                int n = 2 * o + c;
                int gid = n & 7, nt = n >> 3, j = nt >> 1, wsel = nt & 1;
                unsigned u64i =
                    (unsigned)(((((md * 2 + s) * 4 + ks) * 4 + j) * 32
                                + (gid * 4 + t4)) * 2 + wsel);
                unsigned val = c ? ((p >> 16) | (p << 16))    // (wi, wr)
                                 : (p ^ 0x80000000u);         // (wr, -wi)
                dst[u64i * 2 + half] = val;
            }
        }
    }
}

// ---- main ----
__global__ void __launch_bounds__(THREADS, 1)
spectral_r12_kernel(const float* __restrict__ X,
                    float* __restrict__ O)
{
    extern __shared__ char smem[];
    const unsigned sb = smem_u32(smem);

    const int tid  = threadIdx.x;
    const int lane = tid & 31;
    const int md   = tid >> 5;                  // warp == mode
    const int gid  = lane >> 2;
    const int t4   = lane & 3;
    const int kgi  = blockIdx.y;
    const int kg   = kgi * KT;
    const long rowBase = (long)blockIdx.x * (TROWS * TILES);

    // fill tile t (raw fp32 pairs; 16B = 2 modes, slot-swizzled)
    auto fill = [&](int t, unsigned buf) {
        const float* base = X + (rowBase + (long)t * TROWS) * 4096 + (size_t)kg * 2;
        #pragma unroll
        for (int it = 0; it < 16; ++it) {
            int idx = tid + it * THREADS;       // 4096 = (row, i, md2)
            int md2 = idx & 3, i = (idx >> 2) & 31, row = idx >> 7;
            cp_async16(buf + (unsigned)(row * RS + i * 8 + ((2 * md2) ^ (i & 6))) * 8,
                       base + (size_t)row * 4096 + i * 128 + md2 * 4);
        }
        cp_commit();
    };

    fill(0, sb);
    fill(1, sb + BUFB);

    const unsigned long long* Bk = gB + kgi * 16384;

    #pragma unroll 1
    for (int t = 0; t < TILES; ++t) {
        const unsigned cur = sb + (unsigned)(t & 1) * BUFB;
        char* curp = smem + (size_t)(t & 1) * BUFB;

        if (t == TILES - 1) cp_wait0(); else cp_wait1();
        __syncthreads();

        float acc[2][8][4];
        #pragma unroll
        for (int mt = 0; mt < 2; ++mt)
            #pragma unroll
            for (int nt = 0; nt < 8; ++nt)
                #pragma unroll
                for (int q = 0; q < 4; ++q) acc[mt][nt][q] = 0.0f;

        #pragma unroll
        for (int ks = 0; ks < 4; ++ks) {
            // B fragments: lane-consecutive LDG.128 (L1-resident), transient
            const ulonglong2* bh2 = reinterpret_cast<const ulonglong2*>(
                Bk + (size_t)((((md * 2 + 0) * 4 + ks) * 4) * 32 + lane) * 2);
            const ulonglong2* bl2 = reinterpret_cast<const ulonglong2*>(
                Bk + (size_t)((((md * 2 + 1) * 4 + ks) * 4) * 32 + lane) * 2);
            ulonglong2 BH[4], BL[4];
            #pragma unroll
            for (int j = 0; j < 4; ++j) { BH[j] = bh2[j * 32]; BL[j] = bl2[j * 32]; }

            // A fragments: raw fp32 LDS.64 + split-at-use
            unsigned ah[2][4], al[2][4];
            #pragma unroll
            for (int mt = 0; mt < 2; ++mt)
                #pragma unroll
                for (int j = 0; j < 4; ++j) {
                    int row = mt * 16 + gid + (j & 1) * 8;
                    int i   = t4 + (j >> 1) * 4 + 8 * ks;
                    unsigned long long v = lds64(
                        cur + (unsigned)(row * RS + i * 8 + (md ^ (i & 6))) * 8);
                    float xr, xi;
                    asm("mov.b64 {%0,%1}, %2;" : "=f"(xr), "=f"(xi) : "l"(v));
                    unsigned ph = cvt2bf(xr, xi);
                    float xrh = __uint_as_float(ph << 16);
                    float xih = __uint_as_float(ph & 0xFFFF0000u);
                    ah[mt][j] = ph;
                    al[mt][j] = cvt2bf(xr - xrh, xi - xih);
                }

            #pragma unroll
            for (int nt = 0; nt < 8; ++nt) {
                unsigned long long bh = (nt & 1) ? BH[nt >> 1].y : BH[nt >> 1].x;
                unsigned long long bl = (nt & 1) ? BL[nt >> 1].y : BL[nt >> 1].x;
                unsigned bh0 = (unsigned)bh, bh1 = (unsigned)(bh >> 32);
                unsigned bl0 = (unsigned)bl, bl1 = (unsigned)(bl >> 32);
                #pragma unroll
                for (int mt = 0; mt < 2; ++mt) {
                    mma16816(acc[mt][nt], ah[mt], bh0, bh1);   // hi*hi
                    mma16816(acc[mt][nt], al[mt], bh0, bh1);   // lo*hi
                    mma16816(acc[mt][nt], ah[mt], bl0, bl1);   // hi*lo
                }
            }
        }
        __syncthreads();        // reads of cur done -> reuse as out stage

        // out stage: [row][o][mdslot] u64 = (Re,Im), slot = md ^ (o&6)
        #pragma unroll
        for (int mt = 0; mt < 2; ++mt)
            #pragma unroll
            for (int nt = 0; nt < 8; ++nt) {
                int o = nt * 4 + t4;
                unsigned so = (unsigned)(o * 8 + (md ^ (o & 6)));
                int r0 = mt * 16 + gid;
                sts64(cur + (unsigned)(r0 * RS) * 8 + so * 8,
                      pack2(acc[mt][nt][0], acc[mt][nt][1]));
                sts64(cur + (unsigned)((r0 + 8) * RS) * 8 + so * 8,
                      pack2(acc[mt][nt][2], acc[mt][nt][3]));
            }
        __syncthreads();

        // coalesced store: per (row,o) 64B k-run; chunk q -> k = (2q)^(o&6)
        const long trow = rowBase + (long)t * TROWS;
        #pragma unroll
        for (int it = 0; it < 16; ++it) {
            int g = tid + it * THREADS;         // 4096 = (row, o, q)
            int q = g & 3, o = (g >> 2) & 31, row = g >> 7;
            ulonglong2 v = *reinterpret_cast<ulonglong2*>(
                curp + (size_t)(row * RS + o * 8 + q * 2) * 8);
            *reinterpret_cast<ulonglong2*>(
                O + (trow + row) * 4096 + (size_t)o * 128
                  + (size_t)(kg + ((2 * q) ^ (o & 6))) * 2) = v;
        }

        if (t + 2 < TILES) {
            __syncthreads();    // STG reads done before refilling cur
            fill(t + 2, cur);
        }
    }
}

extern "C" void kernel_launch(void* const* d_in, const int* in_sizes, int n_in,
                              void* d_out, int out_size)
{
    const float* x = (const float*)d_in[0];   // (8,2048,32,64,2) fp32
    const float* w = (const float*)d_in[1];   // (32,32,64,2) fp32
    float* out = (float*)d_out;               // (8,2048,32,64,2) fp32

    spectral_prepB_kernel<<<8, THREADS>>>(w);

    cudaFuncSetAttribute(spectral_r12_kernel,
                         cudaFuncAttributeMaxDynamicSharedMemorySize, SMEM_BYTES);
    dim3 grid(16384 / (TROWS * TILES), 64 / KT);   // (128, 8) = 1024 CTAs
    spectral_r12_kernel<<<grid, THREADS, SMEM_BYTES>>>(x, out);
}